// round 2
// baseline (speedup 1.0000x reference)
#include <cuda_runtime.h>
#include <cstdint>

// ElasticEmbedding: out[t] = residual_embedding[r] if token x[t] is in
// residual_index (rightmost slot r, last-occurrence-wins), else
// pretrained_embedding[x[t]].
//
// Inputs (metadata order) — NOTE: JAX without x64 downcasts int64 -> int32:
//   d_in[0]: x                    int32  [B*S]          (32768)
//   d_in[1]: pretrained_embedding fp32   [50257, 768]
//   d_in[2]: residual_embedding   fp32   [5000, 768]
//   d_in[3]: residual_index       int32  [5000] sorted
// Output: fp32 [B*S, 768]
//
// Pure HBM-bound gather: one block per token, 192 threads x float4 = 768 floats.

#ifndef EMBED_DIM
#define EMBED_DIM 768
#endif
#define VEC_PER_ROW (EMBED_DIM / 4)   // 192 float4 per row

__global__ __launch_bounds__(VEC_PER_ROW, 8)
void elastic_embedding_kernel(const int* __restrict__ x,
                              const float4* __restrict__ pre,
                              const float4* __restrict__ res,
                              const int* __restrict__ ridx,
                              float4* __restrict__ out,
                              int n_res)
{
    const int token = blockIdx.x;
    const int v = __ldg(&x[token]);

    // upper_bound over sorted residual_index: lo = first index with ridx[lo] > v.
    // Rightmost match (last occurrence wins) is lo-1 if it equals v.
    int lo = 0, hi = n_res;
    while (lo < hi) {
        int mid = (lo + hi) >> 1;
        int m = __ldg(&ridx[mid]);     // uniform across block -> broadcast, L1/L2-hot
        if (m <= v) lo = mid + 1; else hi = mid;
    }

    const float4* __restrict__ src;
    if (lo > 0 && __ldg(&ridx[lo - 1]) == v) {
        src = res + (long long)(lo - 1) * VEC_PER_ROW;
    } else {
        src = pre + (long long)v * VEC_PER_ROW;
    }

    float4* __restrict__ dst = out + (long long)token * VEC_PER_ROW;
    const int t = threadIdx.x;
    dst[t] = __ldg(&src[t]);
}

extern "C" void kernel_launch(void* const* d_in, const int* in_sizes, int n_in,
                              void* d_out, int out_size)
{
    const int*    x    = (const int*)d_in[0];
    const float4* pre  = (const float4*)d_in[1];
    const float4* res  = (const float4*)d_in[2];
    const int*    ridx = (const int*)d_in[3];
    float4*       out  = (float4*)d_out;

    const int n_tokens = in_sizes[0];          // B*S = 32768
    const int n_res    = in_sizes[3];          // 5000

    elastic_embedding_kernel<<<n_tokens, VEC_PER_ROW>>>(x, pre, res, ridx, out, n_res);
}

// round 3
// speedup vs baseline: 1.5271x; 1.5271x over previous
#include <cuda_runtime.h>
#include <cstdint>

// ElasticEmbedding, two-phase:
//   A) resolve: per-token binary search over sorted residual_index (rightmost
//      match = last-occurrence-wins) -> source row pointer in scratch.
//   B) copy: 8 tokens/block, 192 threads, 8 independent float4 loads per
//      thread (MLP=8) -> DRAM-throughput bound instead of latency bound.
//
// Inputs (metadata order, JAX int64 -> int32 on device):
//   d_in[0]: x                    int32  [32768]
//   d_in[1]: pretrained_embedding fp32   [50257, 768]
//   d_in[2]: residual_embedding   fp32   [5000, 768]
//   d_in[3]: residual_index       int32  [5000] sorted
// Output: fp32 [32768, 768]

#define EMBED_DIM   768
#define VEC_PER_ROW (EMBED_DIM / 4)   // 192 float4 per row
#define MAX_TOKENS  65536
#define TOK_PER_BLK 8

// Scratch: resolved source-row pointer per token (stable across graph replays;
// harness device buffers are fixed).
__device__ const float4* g_src[MAX_TOKENS];

__global__ void resolve_kernel(const int* __restrict__ x,
                               const float4* __restrict__ pre,
                               const float4* __restrict__ res,
                               const int* __restrict__ ridx,
                               int n_tokens, int n_res)
{
    int t = blockIdx.x * blockDim.x + threadIdx.x;
    if (t >= n_tokens) return;
    const int v = __ldg(&x[t]);

    // upper_bound: lo = first index with ridx[lo] > v; rightmost match = lo-1.
    int lo = 0, hi = n_res;
    while (lo < hi) {
        int mid = (lo + hi) >> 1;
        if (__ldg(&ridx[mid]) <= v) lo = mid + 1; else hi = mid;
    }

    const float4* src;
    if (lo > 0 && __ldg(&ridx[lo - 1]) == v)
        src = res + (long long)(lo - 1) * VEC_PER_ROW;
    else
        src = pre + (long long)v * VEC_PER_ROW;
    g_src[t] = src;
}

__global__ __launch_bounds__(VEC_PER_ROW, 6)
void copy_kernel(float4* __restrict__ out, int n_tokens)
{
    const int bt = blockIdx.x * TOK_PER_BLK;   // first token of this block
    const int t  = threadIdx.x;                // 0..191, vec index within row

    if (bt + TOK_PER_BLK <= n_tokens) {
        // Fast path: batch 8 independent row reads -> MLP=8 per thread.
        const float4* s[TOK_PER_BLK];
#pragma unroll
        for (int u = 0; u < TOK_PER_BLK; u++) s[u] = g_src[bt + u];

        float4 v[TOK_PER_BLK];
#pragma unroll
        for (int u = 0; u < TOK_PER_BLK; u++) v[u] = __ldg(&s[u][t]);

#pragma unroll
        for (int u = 0; u < TOK_PER_BLK; u++)
            out[(long long)(bt + u) * VEC_PER_ROW + t] = v[u];
    } else {
        for (int u = 0; u < TOK_PER_BLK; u++) {
            int tok = bt + u;
            if (tok >= n_tokens) break;
            out[(long long)tok * VEC_PER_ROW + t] = __ldg(&g_src[tok][t]);
        }
    }
}

extern "C" void kernel_launch(void* const* d_in, const int* in_sizes, int n_in,
                              void* d_out, int out_size)
{
    const int*    x    = (const int*)d_in[0];
    const float4* pre  = (const float4*)d_in[1];
    const float4* res  = (const float4*)d_in[2];
    const int*    ridx = (const int*)d_in[3];
    float4*       out  = (float4*)d_out;

    const int n_tokens = in_sizes[0];          // 32768
    const int n_res    = in_sizes[3];          // 5000

    resolve_kernel<<<(n_tokens + 255) / 256, 256>>>(x, pre, res, ridx,
                                                    n_tokens, n_res);

    const int n_blocks = (n_tokens + TOK_PER_BLK - 1) / TOK_PER_BLK;
    copy_kernel<<<n_blocks, VEC_PER_ROW>>>(out, n_tokens);
}

// round 4
// speedup vs baseline: 1.6959x; 1.1105x over previous
#include <cuda_runtime.h>
#include <cstdint>

// ElasticEmbedding, remap-table two-phase:
//   A) scatter: remap[ridx[i]] = max(i+1)  (sorted -> max = last occurrence;
//      zero-initialized device global -> 0 means "not residual"; idempotent
//      across graph replays).
//   B) copy: 8 tokens/block, 192 threads. Per token: 2-deep lookup
//      (x -> remap) resolves source row; 8 independent float4 loads (MLP=8)
//      then 8 streaming stores.
//
// Inputs (metadata order, JAX int64 -> int32 on device):
//   d_in[0]: x                    int32  [32768]
//   d_in[1]: pretrained_embedding fp32   [50257, 768]
//   d_in[2]: residual_embedding   fp32   [5000, 768]
//   d_in[3]: residual_index       int32  [5000] sorted
// Output: fp32 [32768, 768]

#define EMBED_DIM   768
#define VEC_PER_ROW (EMBED_DIM / 4)   // 192 float4 per row
#define VOCAB_MAX   65536
#define TOK_PER_BLK 8

// remap[v] = slot+1 of last occurrence of v in residual_index, or 0.
// Zero-initialized at module load; scatter_kernel writes are idempotent.
__device__ int g_remap[VOCAB_MAX];

__global__ void scatter_kernel(const int* __restrict__ ridx, int n_res)
{
    int i = blockIdx.x * blockDim.x + threadIdx.x;
    if (i < n_res) {
        atomicMax(&g_remap[__ldg(&ridx[i])], i + 1);
    }
}

__global__ __launch_bounds__(VEC_PER_ROW, 7)
void copy_kernel(const int* __restrict__ x,
                 const float4* __restrict__ pre,
                 const float4* __restrict__ res,
                 float4* __restrict__ out,
                 int n_tokens)
{
    const int bt = blockIdx.x * TOK_PER_BLK;
    const int t  = threadIdx.x;               // 0..191

    if (bt + TOK_PER_BLK <= n_tokens) {
        // Resolve 8 tokens -> compact int code: >=0 -> pretrained row v,
        // <0 -> residual slot (-code-1). One int per token keeps regs ~48.
        int code[TOK_PER_BLK];
#pragma unroll
        for (int u = 0; u < TOK_PER_BLK; u++) {
            int v = __ldg(&x[bt + u]);        // broadcast within block
            int r = __ldg(&g_remap[v]);       // broadcast, L2-hot
            code[u] = (r > 0) ? -r : v;       // -r = -(slot+1)
        }

        float4 d[TOK_PER_BLK];
#pragma unroll
        for (int u = 0; u < TOK_PER_BLK; u++) {
            const float4* src = (code[u] < 0)
                ? res + (long long)(-code[u] - 1) * VEC_PER_ROW
                : pre + (long long)code[u] * VEC_PER_ROW;
            d[u] = __ldg(&src[t]);
        }

#pragma unroll
        for (int u = 0; u < TOK_PER_BLK; u++) {
            __stcs(&out[(long long)(bt + u) * VEC_PER_ROW + t], d[u]);
        }
    } else {
        for (int u = 0; u < TOK_PER_BLK; u++) {
            int tok = bt + u;
            if (tok >= n_tokens) break;
            int v = __ldg(&x[tok]);
            int r = __ldg(&g_remap[v]);
            const float4* src = (r > 0)
                ? res + (long long)(r - 1) * VEC_PER_ROW
                : pre + (long long)v * VEC_PER_ROW;
            __stcs(&out[(long long)tok * VEC_PER_ROW + t], __ldg(&src[t]));
        }
    }
}

extern "C" void kernel_launch(void* const* d_in, const int* in_sizes, int n_in,
                              void* d_out, int out_size)
{
    const int*    x    = (const int*)d_in[0];
    const float4* pre  = (const float4*)d_in[1];
    const float4* res  = (const float4*)d_in[2];
    const int*    ridx = (const int*)d_in[3];
    float4*       out  = (float4*)d_out;

    const int n_tokens = in_sizes[0];          // 32768
    const int n_res    = in_sizes[3];          // 5000

    scatter_kernel<<<(n_res + 255) / 256, 256>>>(ridx, n_res);

    const int n_blocks = (n_tokens + TOK_PER_BLK - 1) / TOK_PER_BLK;
    copy_kernel<<<n_blocks, VEC_PER_ROW>>>(x, pre, res, out, n_tokens);
}